// round 8
// baseline (speedup 1.0000x reference)
#include <cuda_runtime.h>
#include <cuda_bf16.h>
#include <cstdint>

#define DEVINL __device__ __forceinline__

// ----------------------------------------------------------------------------
// w_bin as plain fp32 [d][f] row-major (d = K index, f = N index). 64 KB.
// ----------------------------------------------------------------------------
__device__ __align__(16) float g_w[128 * 128];

// ----------------------------------------------------------------------------
// Threefry2x32-20 (exactly JAX's jax._src.prng.threefry2x32 permutation)
// ----------------------------------------------------------------------------
DEVINL uint32_t rotl32(uint32_t x, int r) { return (x << r) | (x >> (32 - r)); }

DEVINL void threefry2x32(uint32_t k0, uint32_t k1, uint32_t& x0, uint32_t& x1) {
    uint32_t ks0 = k0, ks1 = k1, ks2 = k0 ^ k1 ^ 0x1BD11BDAu;
    x0 += ks0; x1 += ks1;
#define TF_ROUND(r) { x0 += x1; x1 = rotl32(x1, r) ^ x0; }
    TF_ROUND(13) TF_ROUND(15) TF_ROUND(26) TF_ROUND(6)
    x0 += ks1; x1 += ks2 + 1u;
    TF_ROUND(17) TF_ROUND(29) TF_ROUND(16) TF_ROUND(24)
    x0 += ks2; x1 += ks0 + 2u;
    TF_ROUND(13) TF_ROUND(15) TF_ROUND(26) TF_ROUND(6)
    x0 += ks0; x1 += ks1 + 3u;
    TF_ROUND(17) TF_ROUND(29) TF_ROUND(16) TF_ROUND(24)
    x0 += ks1; x1 += ks2 + 4u;
    TF_ROUND(13) TF_ROUND(15) TF_ROUND(26) TF_ROUND(6)
    x0 += ks2; x1 += ks0 + 5u;
#undef TF_ROUND
}

// PARTITIONABLE threefry (JAX default since 0.4.30, jax_threefry_partitionable):
// element i gets counter (hi, lo) = (0, i) [uint64 iota], and the 32-bit
// output is the XOR of the two threefry outputs: bits[i] = out0 ^ out1.
__global__ void wbin_kernel(const float* __restrict__ weight,
                            const int* __restrict__ seed_p,
                            const int* __restrict__ train_p) {
    int i = blockIdx.x * blockDim.x + threadIdx.x;
    if (i >= 16384) return;
    float s;
    if (*train_p) {
        uint32_t x0 = 0u, x1 = (uint32_t)i;           // counter = uint64 i
        threefry2x32(0u, (uint32_t)(*seed_p), x0, x1); // key = (0, seed)
        uint32_t bits = x0 ^ x1;                       // 32-bit partitionable output
        // JAX uniform: bitcast(0x3f800000 | bits>>9) - 1.0
        float u = __uint_as_float(0x3f800000u | (bits >> 9)) - 1.0f;
        float w = weight[i];
        float p = fminf(fmaxf(__fmul_rn(__fadd_rn(w, 1.0f), 0.5f), 0.0f), 1.0f);
        s = (u < p) ? 1.0f : -1.0f;
    } else {
        s = (weight[i] > 0.0f) ? 1.0f : -1.0f;
    }
    g_w[i] = s;   // plain [d][f] row-major: lin = d*128 + f
}

// ----------------------------------------------------------------------------
// GEMM: one 128-row tile per CTA, 512 threads.  (unchanged from R7 — it ran)
// Thread t: row = t & 127, f-segment = t >> 7 (32 outputs).
// All lanes of a warp share the f-segment -> w reads are pure broadcast.
// SMEM: w [0, 64K) fp32 [128][128]; A [64K, ...) fp32 [128][129] (pad).
// Inner loop: FFMA2 (fma.rn.f32x2) -> 2 fp32 FMA per instruction.
// ----------------------------------------------------------------------------
static constexpr int SMEM_W_FLOATS = 128 * 128;           // 16384
static constexpr int SMEM_A_STRIDE = 129;                 // conflict-free lane reads
static constexpr int SMEM_TOTAL =
    (SMEM_W_FLOATS + 128 * SMEM_A_STRIDE) * 4;            // 131584 bytes

__global__ void __launch_bounds__(512, 1)
gemm_kernel(const float* __restrict__ inp, float* __restrict__ out) {
    extern __shared__ float sm[];
    float* wsm = sm;                       // [128*128]
    float* asm_ = sm + SMEM_W_FLOATS;      // [128*129]
    const int tid = threadIdx.x;

    // --- w_bin: straight 64 KB copy (L2-resident, shared by all CTAs) ---
    {
        const float4* g = (const float4*)g_w;
        float4* d = (float4*)wsm;
#pragma unroll
        for (int i = 0; i < 8; i++) d[tid + i * 512] = g[tid + i * 512];
    }

    // --- A tile: coalesced float4 loads -> padded rows (stride 129 floats).
    //     Scalar stores only: odd rows sit at 4 mod 8 bytes; st.shared.v2/v4
    //     would trap on misalignment (R5 evidence). ---
    {
        const float4* a4 = (const float4*)(inp + (size_t)blockIdx.x * (128 * 128));
#pragma unroll
        for (int i = 0; i < 8; i++) {
            int idx = tid + i * 512;
            int row = idx >> 5;
            int c4  = idx & 31;
            float4 v = a4[idx];
            float* p = asm_ + row * SMEM_A_STRIDE + c4 * 4;
            p[0] = v.x;
            p[1] = v.y;
            p[2] = v.z;
            p[3] = v.w;
        }
    }
    __syncthreads();

    const int row  = tid & 127;
    const int fseg = tid >> 7;             // 0..3, warp-uniform
    const float* arow = asm_ + row * SMEM_A_STRIDE;
    const uint4* w4base = (const uint4*)wsm + fseg * 8;   // + d*32 per row of w

    unsigned long long acc[16];            // 16 x f32x2 = 32 fp32 outputs
#pragma unroll
    for (int q = 0; q < 16; q++) acc[q] = 0ull;  // (0.0f, 0.0f)

#pragma unroll 4
    for (int d = 0; d < 128; d++) {
        float a = arow[d];
        unsigned long long a2;
        {
            uint32_t au = __float_as_uint(a);
            asm("mov.b64 %0, {%1, %1};" : "=l"(a2) : "r"(au));
        }
        const uint4* wrow = w4base + d * 32;
#pragma unroll
        for (int q = 0; q < 8; q++) {
            uint4 wv = wrow[q];            // 4 w values = 2 f32x2 pairs (broadcast)
            unsigned long long w01, w23;
            asm("mov.b64 %0, {%1, %2};" : "=l"(w01) : "r"(wv.x), "r"(wv.y));
            asm("mov.b64 %0, {%1, %2};" : "=l"(w23) : "r"(wv.z), "r"(wv.w));
            asm("fma.rn.f32x2 %0, %1, %2, %0;" : "+l"(acc[2 * q])     : "l"(a2), "l"(w01));
            asm("fma.rn.f32x2 %0, %1, %2, %0;" : "+l"(acc[2 * q + 1]) : "l"(a2), "l"(w23));
        }
    }

    // --- Epilogue: 8 x STG.128, 128B contiguous per lane (full sectors) ---
    float* orow = out + (size_t)(blockIdx.x * 128 + row) * 128 + fseg * 32;
#pragma unroll
    for (int q = 0; q < 8; q++) {
        float2 p0 = *(float2*)&acc[2 * q];
        float2 p1 = *(float2*)&acc[2 * q + 1];
        *(float4*)(orow + 4 * q) = make_float4(p0.x, p0.y, p1.x, p1.y);
    }
}

// ----------------------------------------------------------------------------
extern "C" void kernel_launch(void* const* d_in, const int* in_sizes, int n_in,
                              void* d_out, int out_size) {
    // Resolve pointers by size (robust to metadata ordering):
    //   inputs: 134217728 elems, weight: 16384, seed & is_training: 1 each (in order)
    int ii = 0, wi = 1, si = 2, ti = 3;
    {
        int small[4]; int ns = 0;
        for (int i = 0; i < n_in; i++) {
            if (in_sizes[i] == 16384) wi = i;
            else if (in_sizes[i] > 100000) ii = i;
            else if (ns < 4) small[ns++] = i;
        }
        if (ns >= 2) { si = small[0]; ti = small[1]; }
        else if (ns == 1) { si = small[0]; ti = small[0]; }
    }
    const float* inputs = (const float*)d_in[ii];
    const float* weight = (const float*)d_in[wi];
    const int*   seed   = (const int*)d_in[si];
    const int*   train  = (const int*)d_in[ti];
    float* out = (float*)d_out;

    int n_rows  = in_sizes[ii] / 128;   // 1048576
    int n_tiles = n_rows / 128;         // 8192

    cudaFuncSetAttribute(gemm_kernel,
                         cudaFuncAttributeMaxDynamicSharedMemorySize, SMEM_TOTAL);

    wbin_kernel<<<64, 256>>>(weight, seed, train);
    gemm_kernel<<<n_tiles, 512, SMEM_TOTAL>>>(inputs, out);
}

// round 9
// speedup vs baseline: 4.4125x; 4.4125x over previous
#include <cuda_runtime.h>
#include <cuda_bf16.h>
#include <cstdint>

#define DEVINL __device__ __forceinline__

// ----------------------------------------------------------------------------
// w_bin pre-packed as mma.sync m16n8k16 B-fragments (bf16, "col" operand).
// Word index: ((kc*16 + nb)*32 + lane)*2 + j   (kc = k/16, nb = n/8, j = k-half)
// 8 * 16 * 32 * 2 words * 4B = 32 KB.
// ----------------------------------------------------------------------------
__device__ __align__(16) unsigned char g_bfrag[32768];

// ----------------------------------------------------------------------------
// Threefry2x32-20 (JAX permutation) — PARTITIONABLE output scheme (proven R8)
// ----------------------------------------------------------------------------
DEVINL uint32_t rotl32(uint32_t x, int r) { return (x << r) | (x >> (32 - r)); }

DEVINL void threefry2x32(uint32_t k0, uint32_t k1, uint32_t& x0, uint32_t& x1) {
    uint32_t ks0 = k0, ks1 = k1, ks2 = k0 ^ k1 ^ 0x1BD11BDAu;
    x0 += ks0; x1 += ks1;
#define TF_ROUND(r) { x0 += x1; x1 = rotl32(x1, r) ^ x0; }
    TF_ROUND(13) TF_ROUND(15) TF_ROUND(26) TF_ROUND(6)
    x0 += ks1; x1 += ks2 + 1u;
    TF_ROUND(17) TF_ROUND(29) TF_ROUND(16) TF_ROUND(24)
    x0 += ks2; x1 += ks0 + 2u;
    TF_ROUND(13) TF_ROUND(15) TF_ROUND(26) TF_ROUND(6)
    x0 += ks0; x1 += ks1 + 3u;
    TF_ROUND(17) TF_ROUND(29) TF_ROUND(16) TF_ROUND(24)
    x0 += ks1; x1 += ks2 + 4u;
    TF_ROUND(13) TF_ROUND(15) TF_ROUND(26) TF_ROUND(6)
    x0 += ks2; x1 += ks0 + 5u;
#undef TF_ROUND
}

// Store w_bin[d][f] (d = K index, f = N index) into B-fragment layout.
// mma.m16n8k16 B ("col"): lane = n*4 + (k%8)/2, reg j = k/8, bf16 half = k%2.
DEVINL void wbin_store(int lin_idx, float s) {
    int d = lin_idx >> 7;      // weight row  -> k
    int f = lin_idx & 127;     // weight col  -> n
    int kc = d >> 4, dk = d & 15;
    int nb = f >> 3, fn = f & 7;
    int j    = dk >> 3;
    int kk   = dk & 7;
    int lane = fn * 4 + (kk >> 1);
    int half = kk & 1;
    uint32_t byte_addr = (uint32_t)((((kc * 16 + nb) * 32 + lane) * 2 + j) * 4 + half * 2);
    *(__nv_bfloat16*)(g_bfrag + byte_addr) = __float2bfloat16_rn(s);
}

// Partitionable threefry: element i -> counter (0, i), bits = out0 ^ out1.
__global__ void wbin_kernel(const float* __restrict__ weight,
                            const int* __restrict__ seed_p,
                            const int* __restrict__ train_p) {
    int i = blockIdx.x * blockDim.x + threadIdx.x;
    if (i >= 16384) return;
    float s;
    if (*train_p) {
        uint32_t x0 = 0u, x1 = (uint32_t)i;
        threefry2x32(0u, (uint32_t)(*seed_p), x0, x1);
        uint32_t bits = x0 ^ x1;
        float u = __uint_as_float(0x3f800000u | (bits >> 9)) - 1.0f;
        float w = weight[i];
        float p = fminf(fmaxf(__fmul_rn(__fadd_rn(w, 1.0f), 0.5f), 0.0f), 1.0f);
        s = (u < p) ? 1.0f : -1.0f;
    } else {
        s = (weight[i] > 0.0f) ? 1.0f : -1.0f;
    }
    wbin_store(i, s);
}

// ----------------------------------------------------------------------------
// mma.sync / ldmatrix helpers
// ----------------------------------------------------------------------------
DEVINL uint32_t smem_u32(const void* p) {
    uint32_t a;
    asm("{ .reg .u64 t; cvta.to.shared.u64 t, %1; cvt.u32.u64 %0, t; }"
        : "=r"(a) : "l"(p));
    return a;
}

DEVINL void ldmatrix_x4(uint32_t& r0, uint32_t& r1, uint32_t& r2, uint32_t& r3,
                        uint32_t addr) {
    asm volatile("ldmatrix.sync.aligned.m8n8.x4.shared.b16 {%0,%1,%2,%3}, [%4];"
                 : "=r"(r0), "=r"(r1), "=r"(r2), "=r"(r3) : "r"(addr));
}

DEVINL void mma_bf16(float& c0, float& c1, float& c2, float& c3,
                     uint32_t a0, uint32_t a1, uint32_t a2, uint32_t a3,
                     uint32_t b0, uint32_t b1) {
    asm volatile(
        "mma.sync.aligned.m16n8k16.row.col.f32.bf16.bf16.f32 "
        "{%0,%1,%2,%3}, {%4,%5,%6,%7}, {%8,%9}, {%0,%1,%2,%3};"
        : "+f"(c0), "+f"(c1), "+f"(c2), "+f"(c3)
        : "r"(a0), "r"(a1), "r"(a2), "r"(a3), "r"(b0), "r"(b1));
}

// ----------------------------------------------------------------------------
// GEMM kernel: one 128x128 output tile per CTA, 256 threads (8 warps).
// Warp w computes rows [16w, 16w+16) x all 128 cols.
// SMEM: A_hi [0,32K), A_lo [32K,64K), B-frags [64K,96K)
// ----------------------------------------------------------------------------
static constexpr int SMEM_A_HI = 0;
static constexpr int SMEM_A_LO = 32768;
static constexpr int SMEM_B    = 65536;
static constexpr int SMEM_TOTAL = 98304;

__global__ void __launch_bounds__(256, 2)
gemm_kernel(const float* __restrict__ inp, float* __restrict__ out) {
    extern __shared__ char smem[];
    const uint32_t smem_base = smem_u32(smem);
    const int tid  = threadIdx.x;
    const int w    = tid >> 5;
    const int lane = tid & 31;

    // --- B fragments: straight 32 KB copy (L2-resident, shared by all CTAs) ---
    {
        const uint4* src = (const uint4*)g_bfrag;
        uint4* dst = (uint4*)(smem + SMEM_B);
#pragma unroll
        for (int i = 0; i < 8; i++) dst[tid + i * 256] = src[tid + i * 256];
    }

    // --- A tile: coalesced float4 loads, split fp32 -> bf16 hi + lo,
    //     row-major bf16 rows (256B) with 32B-granule XOR swizzle.
    //     All SMEM stores are 8B at 8B-aligned offsets (R5 alignment lesson). ---
    {
        const float4* a4 = (const float4*)(inp + (size_t)blockIdx.x * (128 * 128));
#pragma unroll
        for (int i = 0; i < 16; i++) {
            int idx = tid + i * 256;
            int row = idx >> 5;
            int c4  = idx & 31;       // float4 index within row
            float4 v = a4[idx];
            __nv_bfloat162 h01, h23, l01, l23;
            h01.x = __float2bfloat16_rn(v.x); h01.y = __float2bfloat16_rn(v.y);
            h23.x = __float2bfloat16_rn(v.z); h23.y = __float2bfloat16_rn(v.w);
            l01.x = __float2bfloat16_rn(v.x - __bfloat162float(h01.x));
            l01.y = __float2bfloat16_rn(v.y - __bfloat162float(h01.y));
            l23.x = __float2bfloat16_rn(v.z - __bfloat162float(h23.x));
            l23.y = __float2bfloat16_rn(v.w - __bfloat162float(h23.y));
            uint32_t off = (uint32_t)(row * 256 + ((((c4 >> 2) ^ (row & 7))) << 5) +
                                      ((c4 & 3) << 3));
            *(uint2*)(smem + SMEM_A_HI + off) =
                make_uint2(*(uint32_t*)&h01, *(uint32_t*)&h23);
            *(uint2*)(smem + SMEM_A_LO + off) =
                make_uint2(*(uint32_t*)&l01, *(uint32_t*)&l23);
        }
    }
    __syncthreads();

    // --- ldmatrix per-lane base address for this warp's 16-row slice ---
    // lane -> (row = 16w + (lane & 15), 16B k-half = lane >> 4)
    const int arow = 16 * w + (lane & 15);
    const uint32_t a_row_off = (uint32_t)(arow * 256 + ((lane >> 4) << 4));
    const uint32_t a_sw = (uint32_t)(arow & 7);

    const uint2* bfr = (const uint2*)(smem + SMEM_B);

    float c[16][4];
#pragma unroll
    for (int nb = 0; nb < 16; nb++)
#pragma unroll
        for (int q = 0; q < 4; q++) c[nb][q] = 0.0f;

    // --- Main loop over K chunks ---
#pragma unroll
    for (int kc = 0; kc < 8; kc++) {
        uint32_t koff = (uint32_t)(((uint32_t)kc ^ a_sw) << 5);
        uint32_t ah0, ah1, ah2, ah3, al0, al1, al2, al3;
        ldmatrix_x4(ah0, ah1, ah2, ah3, smem_base + SMEM_A_HI + a_row_off + koff);
        ldmatrix_x4(al0, al1, al2, al3, smem_base + SMEM_A_LO + a_row_off + koff);
#pragma unroll
        for (int nb = 0; nb < 16; nb++) {
            uint2 b = bfr[(kc * 16 + nb) * 32 + lane];
            mma_bf16(c[nb][0], c[nb][1], c[nb][2], c[nb][3],
                     ah0, ah1, ah2, ah3, b.x, b.y);
            mma_bf16(c[nb][0], c[nb][1], c[nb][2], c[nb][3],
                     al0, al1, al2, al3, b.x, b.y);
        }
    }

    // --- Epilogue: direct STG.64 (8-row x 32B segments, full sectors) ---
    {
        const int r0 = (int)(blockIdx.x * 128) + 16 * w + (lane >> 2);
        const int cb = 2 * (lane & 3);
        float* o0 = out + (size_t)r0 * 128 + cb;
        float* o1 = o0 + (size_t)8 * 128;
#pragma unroll
        for (int nb = 0; nb < 16; nb++) {
            *(float2*)(o0 + nb * 8) = make_float2(c[nb][0], c[nb][1]);
            *(float2*)(o1 + nb * 8) = make_float2(c[nb][2], c[nb][3]);
        }
    }
}

// ----------------------------------------------------------------------------
extern "C" void kernel_launch(void* const* d_in, const int* in_sizes, int n_in,
                              void* d_out, int out_size) {
    // Resolve pointers by size (robust to metadata ordering).
    int ii = 0, wi = 1, si = 2, ti = 3;
    {
        int small[4]; int ns = 0;
        for (int i = 0; i < n_in; i++) {
            if (in_sizes[i] == 16384) wi = i;
            else if (in_sizes[i] > 100000) ii = i;
            else if (ns < 4) small[ns++] = i;
        }
        if (ns >= 2) { si = small[0]; ti = small[1]; }
        else if (ns == 1) { si = small[0]; ti = small[0]; }
    }
    const float* inputs = (const float*)d_in[ii];
    const float* weight = (const float*)d_in[wi];
    const int*   seed   = (const int*)d_in[si];
    const int*   train  = (const int*)d_in[ti];
    float* out = (float*)d_out;

    int n_rows  = in_sizes[ii] / 128;   // 1048576
    int n_tiles = n_rows / 128;         // 8192

    cudaFuncSetAttribute(gemm_kernel,
                         cudaFuncAttributeMaxDynamicSharedMemorySize, SMEM_TOTAL);

    wbin_kernel<<<64, 256>>>(weight, seed, train);
    gemm_kernel<<<n_tiles, 256, SMEM_TOTAL>>>(inputs, out);
}

// round 11
// speedup vs baseline: 5.0252x; 1.1388x over previous
#include <cuda_runtime.h>
#include <cuda_bf16.h>
#include <cstdint>

#define DEVINL __device__ __forceinline__

// ----------------------------------------------------------------------------
// w_bin pre-packed as mma.sync m16n8k16 B-fragments (bf16, "col" operand).
// Word index: ((kc*16 + nb)*32 + lane)*2 + j   (kc = k/16, nb = n/8, j = k-half)
// 32 KB total.  (Layout validated by R9's rel_err = 2.5e-6 pass.)
// ----------------------------------------------------------------------------
__device__ __align__(16) unsigned char g_bfrag[32768];

// ----------------------------------------------------------------------------
// Threefry2x32-20 (JAX permutation) — PARTITIONABLE output scheme (proven R8)
// ----------------------------------------------------------------------------
DEVINL uint32_t rotl32(uint32_t x, int r) { return (x << r) | (x >> (32 - r)); }

DEVINL void threefry2x32(uint32_t k0, uint32_t k1, uint32_t& x0, uint32_t& x1) {
    uint32_t ks0 = k0, ks1 = k1, ks2 = k0 ^ k1 ^ 0x1BD11BDAu;
    x0 += ks0; x1 += ks1;
#define TF_ROUND(r) { x0 += x1; x1 = rotl32(x1, r) ^ x0; }
    TF_ROUND(13) TF_ROUND(15) TF_ROUND(26) TF_ROUND(6)
    x0 += ks1; x1 += ks2 + 1u;
    TF_ROUND(17) TF_ROUND(29) TF_ROUND(16) TF_ROUND(24)
    x0 += ks2; x1 += ks0 + 2u;
    TF_ROUND(13) TF_ROUND(15) TF_ROUND(26) TF_ROUND(6)
    x0 += ks0; x1 += ks1 + 3u;
    TF_ROUND(17) TF_ROUND(29) TF_ROUND(16) TF_ROUND(24)
    x0 += ks1; x1 += ks2 + 4u;
    TF_ROUND(13) TF_ROUND(15) TF_ROUND(26) TF_ROUND(6)
    x0 += ks2; x1 += ks0 + 5u;
#undef TF_ROUND
}

// Store w_bin[d][f] (d = K index, f = N index) into B-fragment layout.
DEVINL void wbin_store(int lin_idx, float s) {
    int d = lin_idx >> 7;      // weight row  -> k
    int f = lin_idx & 127;     // weight col  -> n
    int kc = d >> 4, dk = d & 15;
    int nb = f >> 3, fn = f & 7;
    int j    = dk >> 3;
    int kk   = dk & 7;
    int lane = fn * 4 + (kk >> 1);
    int half = kk & 1;
    uint32_t byte_addr = (uint32_t)((((kc * 16 + nb) * 32 + lane) * 2 + j) * 4 + half * 2);
    *(__nv_bfloat16*)(g_bfrag + byte_addr) = __float2bfloat16_rn(s);
}

// Partitionable threefry: element i -> counter (0, i), bits = out0 ^ out1.
__global__ void wbin_kernel(const float* __restrict__ weight,
                            const int* __restrict__ seed_p,
                            const int* __restrict__ train_p) {
    int i = blockIdx.x * blockDim.x + threadIdx.x;
    if (i >= 16384) return;
    float s;
    if (*train_p) {
        uint32_t x0 = 0u, x1 = (uint32_t)i;
        threefry2x32(0u, (uint32_t)(*seed_p), x0, x1);
        uint32_t bits = x0 ^ x1;
        float u = __uint_as_float(0x3f800000u | (bits >> 9)) - 1.0f;
        float w = weight[i];
        float p = fminf(fmaxf(__fmul_rn(__fadd_rn(w, 1.0f), 0.5f), 0.0f), 1.0f);
        s = (u < p) ? 1.0f : -1.0f;
    } else {
        s = (weight[i] > 0.0f) ? 1.0f : -1.0f;
    }
    wbin_store(i, s);
}

// ----------------------------------------------------------------------------
// mma + conversion helpers
// ----------------------------------------------------------------------------
DEVINL void mma_bf16(float& c0, float& c1, float& c2, float& c3,
                     uint32_t a0, uint32_t a1, uint32_t a2, uint32_t a3,
                     uint32_t b0, uint32_t b1) {
    asm volatile(
        "mma.sync.aligned.m16n8k16.row.col.f32.bf16.bf16.f32 "
        "{%0,%1,%2,%3}, {%4,%5,%6,%7}, {%8,%9}, {%0,%1,%2,%3};"
        : "+f"(c0), "+f"(c1), "+f"(c2), "+f"(c3)
        : "r"(a0), "r"(a1), "r"(a2), "r"(a3), "r"(b0), "r"(b1));
}

// Split (x, y) fp32 pair into packed bf16x2 hi and lo (residual) words.
// hi = rn(x),rn(y); lo = rn(x - f32(hi.x)), rn(y - f32(hi.y)).
// f32(bf16) reconstruction via PRMT (bf16 bits << 16).
DEVINL void split_pair(float x, float y, uint32_t& h, uint32_t& l) {
    asm("cvt.rn.bf16x2.f32 %0, %1, %2;" : "=r"(h) : "f"(y), "f"(x));
    uint32_t hxu, hyu;
    asm("prmt.b32 %0, %1, 0, 0x1044;" : "=r"(hxu) : "r"(h));  // f32 of low bf16
    asm("prmt.b32 %0, %1, 0, 0x3244;" : "=r"(hyu) : "r"(h));  // f32 of high bf16
    float rx = __fsub_rn(x, __uint_as_float(hxu));
    float ry = __fsub_rn(y, __uint_as_float(hyu));
    asm("cvt.rn.bf16x2.f32 %0, %1, %2;" : "=r"(l) : "f"(ry), "f"(rx));
}

// ----------------------------------------------------------------------------
// GEMM kernel: one 128x128 output tile per CTA, 256 threads (8 warps).
// Warp w computes rows [16w, 16w+16) x all 128 cols.
// A is loaded DIRECTLY from GMEM in fragment layout (no SMEM, no ldmatrix):
//   lane l, chunk kc: rows 16w + l/4 and +8, cols kc*16 + 2(l&3) (+1) and +8.
//   Lanes 0-3 cover one full 32B sector of a row; across kc the full row is
//   consumed exactly once -> 100% sector efficiency.
// Only B lives in SMEM (32 KB, one copy, one sync).
// ----------------------------------------------------------------------------
__global__ void __launch_bounds__(256, 2)
gemm_kernel(const float* __restrict__ inp, float* __restrict__ out) {
    __shared__ __align__(16) unsigned char smemB[32768];
    const int tid  = threadIdx.x;
    const int w    = tid >> 5;
    const int lane = tid & 31;

    // --- B fragments: straight 32 KB copy (L2-resident, shared by all CTAs) ---
    {
        const uint4* src = (const uint4*)g_bfrag;
        uint4* dst = (uint4*)smemB;
#pragma unroll
        for (int i = 0; i < 8; i++) dst[tid + i * 256] = src[tid + i * 256];
    }
    __syncthreads();

    const int r0 = 16 * w + (lane >> 2);
    const float* a0p = inp + (size_t)blockIdx.x * 16384 + (size_t)r0 * 128 + (lane & 3) * 2;
    const float* a8p = a0p + 8 * 128;
    const uint2* bfr = (const uint2*)smemB;

    float c[16][4];
#pragma unroll
    for (int nb = 0; nb < 16; nb++)
#pragma unroll
        for (int q = 0; q < 4; q++) c[nb][q] = 0.0f;

    // Prefetched A pairs: x00 = (r0, k+0..1), x01 = (r0, k+8..9),
    //                     x10 = (r0+8, k+0..1), x11 = (r0+8, k+8..9)
    float2 x00 = __ldcs((const float2*)(a0p));
    float2 x01 = __ldcs((const float2*)(a0p + 8));
    float2 x10 = __ldcs((const float2*)(a8p));
    float2 x11 = __ldcs((const float2*)(a8p + 8));

#pragma unroll
    for (int kc = 0; kc < 8; kc++) {
        float2 n00, n01, n10, n11;
        if (kc < 7) {
            const float* p0 = a0p + (kc + 1) * 16;
            const float* p8 = a8p + (kc + 1) * 16;
            n00 = __ldcs((const float2*)(p0));
            n01 = __ldcs((const float2*)(p0 + 8));
            n10 = __ldcs((const float2*)(p8));
            n11 = __ldcs((const float2*)(p8 + 8));
        }

        // Fragment order: a0=(r0,k0) a1=(r0+8,k0) a2=(r0,k8) a3=(r0+8,k8)
        uint32_t ah0, ah1, ah2, ah3, al0, al1, al2, al3;
        split_pair(x00.x, x00.y, ah0, al0);
        split_pair(x10.x, x10.y, ah1, al1);
        split_pair(x01.x, x01.y, ah2, al2);
        split_pair(x11.x, x11.y, ah3, al3);

        const uint2* bk = bfr + kc * 16 * 32 + lane;
#pragma unroll
        for (int nb = 0; nb < 16; nb++) {
            uint2 b = bk[nb * 32];
            mma_bf16(c[nb][0], c[nb][1], c[nb][2], c[nb][3],
                     ah0, ah1, ah2, ah3, b.x, b.y);
            mma_bf16(c[nb][0], c[nb][1], c[nb][2], c[nb][3],
                     al0, al1, al2, al3, b.x, b.y);
        }

        x00 = n00; x01 = n01; x10 = n10; x11 = n11;
    }

    // --- Epilogue: direct streaming STG.64 (full 32B sectors per 4 lanes) ---
    {
        const int orow = (int)(blockIdx.x * 128) + 16 * w + (lane >> 2);
        const int cb = 2 * (lane & 3);
        float* o0 = out + (size_t)orow * 128 + cb;
        float* o1 = o0 + (size_t)8 * 128;
#pragma unroll
        for (int nb = 0; nb < 16; nb++) {
            __stcs((float2*)(o0 + nb * 8), make_float2(c[nb][0], c[nb][1]));
            __stcs((float2*)(o1 + nb * 8), make_float2(c[nb][2], c[nb][3]));
        }
    }
}

// ----------------------------------------------------------------------------
extern "C" void kernel_launch(void* const* d_in, const int* in_sizes, int n_in,
                              void* d_out, int out_size) {
    // Resolve pointers by size (robust to metadata ordering).
    int ii = 0, wi = 1, si = 2, ti = 3;
    {
        int small[4]; int ns = 0;
        for (int i = 0; i < n_in; i++) {
            if (in_sizes[i] == 16384) wi = i;
            else if (in_sizes[i] > 100000) ii = i;
            else if (ns < 4) small[ns++] = i;
        }
        if (ns >= 2) { si = small[0]; ti = small[1]; }
        else if (ns == 1) { si = small[0]; ti = small[0]; }
    }
    const float* inputs = (const float*)d_in[ii];
    const float* weight = (const float*)d_in[wi];
    const int*   seed   = (const int*)d_in[si];
    const int*   train  = (const int*)d_in[ti];
    float* out = (float*)d_out;

    int n_rows  = in_sizes[ii] / 128;   // 1048576
    int n_tiles = n_rows / 128;         // 8192

    wbin_kernel<<<64, 256>>>(weight, seed, train);
    gemm_kernel<<<n_tiles, 256>>>(inputs, out);
}